// round 1
// baseline (speedup 1.0000x reference)
#include <cuda_runtime.h>
#include <cstdint>

#define B_ 32
#define C_ 4
#define H_ 512
#define W_ 512
#define T_ 64
#define NCH 8          // H chunks for diff partials (512/64)
#define PITCH 514      // smem row pitch in float2 (conflict mitigation)

// ------- scratch (static device globals; no allocation) -------
__device__ float  g_part[B_ * 2 * NCH * W_];     // diff partial sums
__device__ int    g_sel [B_ * 2 * T_];           // selected column idx per (b,g)
__device__ float2 g_Y   [B_ * C_ * H_ * T_];     // ifft_H of selected cols, layout (bc, h, t)
__device__ float2 g_tw  [512];                   // forward twiddles e^{-2pi i n/512}

// ------- complex helpers -------
__device__ __forceinline__ float2 cadd(float2 a, float2 b){ return make_float2(a.x+b.x, a.y+b.y); }
__device__ __forceinline__ float2 csub(float2 a, float2 b){ return make_float2(a.x-b.x, a.y-b.y); }
__device__ __forceinline__ float2 cmul(float2 a, float2 b){
    return make_float2(fmaf(a.x, b.x, -a.y*b.y), fmaf(a.x, b.y, a.y*b.x));
}
// multiply by SGN*i
template<int SGN> __device__ __forceinline__ float2 mulj(float2 a){
    return (SGN > 0) ? make_float2(-a.y, a.x) : make_float2(a.y, -a.x);
}

// 4-point DFT, sign SGN (+1 inverse, -1 forward)
template<int SGN> __device__ __forceinline__
void dft4(float2 x0, float2 x1, float2 x2, float2 x3, float2* y){
    float2 t0 = cadd(x0, x2), t1 = csub(x0, x2);
    float2 t2 = cadd(x1, x3), t3 = csub(x1, x3);
    y[0] = cadd(t0, t2);  y[2] = csub(t0, t2);
    float2 j3 = mulj<SGN>(t3);
    y[1] = cadd(t1, j3);  y[3] = csub(t1, j3);
}

// 8-point DFT via DIT split (exact roots, 2 nontrivial cmuls)
template<int SGN> __device__ __forceinline__
void dft8(const float2* a, float2* b){
    float2 E[4], O[4];
    dft4<SGN>(a[0], a[2], a[4], a[6], E);
    dft4<SGN>(a[1], a[3], a[5], a[7], O);
    const float c = 0.70710678118654752440f;
    const float sc = (SGN > 0) ? c : -c;
    float2 o1 = cmul(O[1], make_float2( c, sc));
    float2 o2 = mulj<SGN>(O[2]);
    float2 o3 = cmul(O[3], make_float2(-c, sc));
    b[0] = cadd(E[0], O[0]);  b[4] = csub(E[0], O[0]);
    b[1] = cadd(E[1], o1);    b[5] = csub(E[1], o1);
    b[2] = cadd(E[2], o2);    b[6] = csub(E[2], o2);
    b[3] = cadd(E[3], o3);    b[7] = csub(E[3], o3);
}

// 512-pt FFT over A[0..511] (one FFT per 64 threads, u = lane-in-fft).
// Output left in A in natural order. tw = forward twiddle table (smem).
// All 512 threads of the block must call this together (contains __syncthreads).
template<int SGN> __device__ __forceinline__
void fft512(float2* A, const float2* tw, int u){
    float2 a[8], b[8];
    // ---- stage 1: thread owns slots {u + 64q}
    #pragma unroll
    for(int q = 0; q < 8; q++) a[q] = A[u + 64*q];
    dft8<SGN>(a, b);
    #pragma unroll
    for(int k0 = 0; k0 < 8; k0++){
        float2 w = tw[(u * k0) & 511];
        if(SGN > 0) w.y = -w.y;
        A[u + 64*k0] = cmul(b[k0], w);
    }
    __syncthreads();
    // ---- stage 2: thread = (k0, n2)
    int k0 = u >> 3, n2 = u & 7;
    float2* base = A + 64*k0;
    #pragma unroll
    for(int p = 0; p < 8; p++) a[p] = base[n2 + 8*p];
    dft8<SGN>(a, b);
    #pragma unroll
    for(int k1 = 0; k1 < 8; k1++){
        float2 w = tw[(8 * n2 * k1) & 511];
        if(SGN > 0) w.y = -w.y;
        base[n2 + 8*k1] = cmul(b[k1], w);
    }
    __syncthreads();
    // ---- stage 3: thread = (k0, k1), plain 8-pt DFT, digit-reversed store -> natural order
    int k1 = u & 7;
    #pragma unroll
    for(int n = 0; n < 8; n++) a[n] = A[n + 8*k1 + 64*k0];
    dft8<SGN>(a, b);
    __syncthreads();
    #pragma unroll
    for(int k2 = 0; k2 < 8; k2++) A[k0 + 8*k1 + 64*k2] = b[k2];
    __syncthreads();
}

// ------- kernel 0: twiddle init (sincospif only here) -------
__global__ void k_twinit(){
    int n = threadIdx.x;
    float s, c;
    sincospif((float)n * (1.0f/256.0f), &s, &c);   // angle = 2*pi*n/512
    g_tw[n] = make_float2(c, -s);                   // e^{-2pi i n/512}
}

// ------- kernel 1: diff partial sums over H chunks (deterministic) -------
__global__ void k_diff(const float* __restrict__ xr, const float* __restrict__ xi){
    int blk = blockIdx.x;                 // B*2*NCH = 512 blocks
    int ch  = blk & (NCH-1);
    int bg  = blk >> 3;                   // b*2 + g
    int b   = bg >> 1, g = bg & 1;
    int w   = threadIdx.x;
    size_t base0 = ((size_t)(b*4 + 2*g    ) * H_) * W_;
    size_t base1 = ((size_t)(b*4 + 2*g + 1) * H_) * W_;
    float acc = 0.f;
    int h0 = ch * (H_/NCH);
    #pragma unroll 4
    for(int h = h0; h < h0 + H_/NCH; h++){
        float r0 = xr[base0 + (size_t)h*W_ + w];
        float i0 = xi[base0 + (size_t)h*W_ + w];
        float r1 = xr[base1 + (size_t)h*W_ + w];
        float i1 = xi[base1 + (size_t)h*W_ + w];
        acc += fabsf(fabsf(r0) - fabsf(i1)) + fabsf(fabsf(r1) - fabsf(i0));
    }
    g_part[((size_t)bg * NCH + ch) * W_ + w] = acc;
}

// ------- kernel 2: exact stable top-64 (rank = perfect compaction slot) -------
__global__ void k_select(){
    __shared__ float d[W_];
    int bg = blockIdx.x;                  // 64 blocks
    int w  = threadIdx.x;
    float s = 0.f;
    #pragma unroll
    for(int ch = 0; ch < NCH; ch++)       // fixed order -> deterministic
        s += g_part[((size_t)bg * NCH + ch) * W_ + w];
    d[w] = s;
    __syncthreads();
    int rank = 0;
    for(int j = 0; j < W_; j++){
        float dj = d[j];
        rank += (dj < s) || (dj == s && j < w);   // stable ascending (matches argsort)
    }
    if(rank < T_) g_sel[bg * T_ + rank] = w;
}

// ------- kernel 3: ifft_H of selected columns -> Y (bc, h, t), coalesced write -------
__global__ void k_colifft(const float* __restrict__ xr, const float* __restrict__ xi){
    __shared__ float2 A[8][PITCH];
    __shared__ float2 tw[512];
    int tid = threadIdx.x;
    tw[tid] = g_tw[tid];
    int f = tid >> 6, u = tid & 63;       // fft-id in block, lane-in-fft
    int blk = blockIdx.x;                 // B*C*T/8 = 1024 blocks
    int bc  = blk >> 3;                   // b*4 + c
    int tg  = blk & 7;
    int b = bc >> 2, c = bc & 3, g = c >> 1;
    int t = tg * 8 + f;
    int j = g_sel[(b*2 + g) * T_ + t];
    __syncthreads();
    const float scale = 1.0f / 512.0f;    // ifft normalization
    float2* Af = A[f];
    #pragma unroll
    for(int q = 0; q < 8; q++){
        int h = u + 64*q;
        size_t off = ((size_t)bc * H_ + h) * W_ + j;
        Af[u + 64*q] = make_float2(xr[off] * scale, xi[off] * scale);
    }
    __syncthreads();
    fft512<+1>(Af, tw, u);
    // transpose write: Y[(bc*512 + k)*64 + t], 8 consecutive t per 64B chunk
    #pragma unroll
    for(int pass = 0; pass < 8; pass++){
        int kk = (tid >> 3) + pass * 64;
        int f2 = tid & 7;
        g_Y[((size_t)bc * H_ + kk) * T_ + tg * 8 + f2] = A[f2][kk];
    }
}

// ------- kernel 4: scatter + fft_W + 0.5, coalesced output -------
__global__ void k_rowfft(const float2* __restrict__ Y, float2* __restrict__ out){
    __shared__ float2 A[8][PITCH];
    __shared__ float2 tw[512];
    __shared__ int jj[T_];
    int tid = threadIdx.x;
    tw[tid] = g_tw[tid];
    int blk = blockIdx.x;                 // B*C*H/8 = 8192 blocks
    int bc  = blk >> 6;
    int hg  = blk & 63;
    int b = bc >> 2, c = bc & 3, g = c >> 1;
    if(tid < T_) jj[tid] = g_sel[(b*2 + g) * T_ + tid];
    int f = tid >> 6, u = tid & 63;
    int h = hg * 8 + f;
    #pragma unroll
    for(int q = 0; q < 8; q++) A[f][u + 64*q] = make_float2(0.f, 0.f);
    __syncthreads();
    // scatter: lane u handles t=u; Y row read is 64 consecutive float2 (coalesced)
    {
        float2 v = Y[((size_t)bc * H_ + h) * T_ + u];
        A[f][jj[u]] = v;
    }
    __syncthreads();
    fft512<-1>(A[f], tw, u);
    float2* op = out + ((size_t)bc * H_ + h) * W_;
    #pragma unroll
    for(int q = 0; q < 8; q++){
        float2 v = A[f][u + 64*q];
        v.x += 0.5f;                      // +0.5 lands on real part
        op[u + 64*q] = v;
    }
}

extern "C" void kernel_launch(void* const* d_in, const int* in_sizes, int n_in,
                              void* d_out, int out_size){
    const float* xr = (const float*)d_in[0];
    const float* xi = (const float*)d_in[1];
    float2* out = (float2*)d_out;

    float2* Yp = nullptr;
    cudaGetSymbolAddress((void**)&Yp, g_Y);

    k_twinit <<<1, 512>>>();
    k_diff   <<<B_ * 2 * NCH, 512>>>(xr, xi);
    k_select <<<B_ * 2, 512>>>();
    k_colifft<<<B_ * C_ * T_ / 8, 512>>>(xr, xi);
    k_rowfft <<<B_ * C_ * H_ / 8, 512>>>(Yp, out);
}

// round 2
// speedup vs baseline: 1.0456x; 1.0456x over previous
#include <cuda_runtime.h>
#include <cstdint>

#define B_ 32
#define C_ 4
#define H_ 512
#define W_ 512
#define T_ 64
#define NPART 32       // diff partials per (b,g): 8 h-chunks x 4 sub-strips
#define PITCH 514      // smem row pitch in float2

// ------- scratch (static device globals; no allocation) -------
__device__ float  g_part[B_ * 2 * NPART * W_];   // diff partial sums
__device__ int    g_sel [B_ * 2 * T_];           // selected cols per (b,g), SORTED by j
__device__ float2 g_Y   [B_ * C_ * H_ * T_];     // ifft_H of selected cols, layout (bc, h, t)
__device__ float2 g_tw  [512];                   // forward twiddles e^{-2pi i n/512}

// ------- complex helpers -------
__device__ __forceinline__ float2 cadd(float2 a, float2 b){ return make_float2(a.x+b.x, a.y+b.y); }
__device__ __forceinline__ float2 csub(float2 a, float2 b){ return make_float2(a.x-b.x, a.y-b.y); }
__device__ __forceinline__ float2 cmul(float2 a, float2 b){
    return make_float2(fmaf(a.x, b.x, -a.y*b.y), fmaf(a.x, b.y, a.y*b.x));
}
template<int SGN> __device__ __forceinline__ float2 mulj(float2 a){
    return (SGN > 0) ? make_float2(-a.y, a.x) : make_float2(a.y, -a.x);
}

template<int SGN> __device__ __forceinline__
void dft4(float2 x0, float2 x1, float2 x2, float2 x3, float2* y){
    float2 t0 = cadd(x0, x2), t1 = csub(x0, x2);
    float2 t2 = cadd(x1, x3), t3 = csub(x1, x3);
    y[0] = cadd(t0, t2);  y[2] = csub(t0, t2);
    float2 j3 = mulj<SGN>(t3);
    y[1] = cadd(t1, j3);  y[3] = csub(t1, j3);
}

template<int SGN> __device__ __forceinline__
void dft8(const float2* a, float2* b){
    float2 E[4], O[4];
    dft4<SGN>(a[0], a[2], a[4], a[6], E);
    dft4<SGN>(a[1], a[3], a[5], a[7], O);
    const float c = 0.70710678118654752440f;
    const float sc = (SGN > 0) ? c : -c;
    float2 o1 = cmul(O[1], make_float2( c, sc));
    float2 o2 = mulj<SGN>(O[2]);
    float2 o3 = cmul(O[3], make_float2(-c, sc));
    b[0] = cadd(E[0], O[0]);  b[4] = csub(E[0], O[0]);
    b[1] = cadd(E[1], o1);    b[5] = csub(E[1], o1);
    b[2] = cadd(E[2], o2);    b[6] = csub(E[2], o2);
    b[3] = cadd(E[3], o3);    b[7] = csub(E[3], o3);
}

// 512-pt FFT (one per 64 threads, u = lane-in-fft). Natural-order output.
// Contains __syncthreads: all 512 block threads must call together.
template<int SGN> __device__ __forceinline__
void fft512(float2* A, const float2* tw, int u){
    float2 a[8], b[8];
    #pragma unroll
    for(int q = 0; q < 8; q++) a[q] = A[u + 64*q];
    dft8<SGN>(a, b);
    #pragma unroll
    for(int k0 = 0; k0 < 8; k0++){
        float2 w = tw[(u * k0) & 511];
        if(SGN > 0) w.y = -w.y;
        A[u + 64*k0] = cmul(b[k0], w);
    }
    __syncthreads();
    int k0 = u >> 3, n2 = u & 7;
    float2* base = A + 64*k0;
    #pragma unroll
    for(int p = 0; p < 8; p++) a[p] = base[n2 + 8*p];
    dft8<SGN>(a, b);
    #pragma unroll
    for(int k1 = 0; k1 < 8; k1++){
        float2 w = tw[(8 * n2 * k1) & 511];
        if(SGN > 0) w.y = -w.y;
        base[n2 + 8*k1] = cmul(b[k1], w);
    }
    __syncthreads();
    int k1 = u & 7;
    #pragma unroll
    for(int n = 0; n < 8; n++) a[n] = A[n + 8*k1 + 64*k0];
    dft8<SGN>(a, b);
    __syncthreads();
    #pragma unroll
    for(int k2 = 0; k2 < 8; k2++) A[k0 + 8*k1 + 64*k2] = b[k2];
    __syncthreads();
}

// ------- kernel 0: twiddle init -------
__global__ void k_twinit(){
    int n = threadIdx.x;
    float s, c;
    sincospif((float)n * (1.0f/256.0f), &s, &c);
    g_tw[n] = make_float2(c, -s);
}

// ------- kernel 1: diff partials, float4 loads -------
__global__ void k_diff(const float* __restrict__ xr, const float* __restrict__ xi){
    int blk = blockIdx.x;                 // bg*8 + ch, 512 blocks
    int ch  = blk & 7;
    int bg  = blk >> 3;
    int b   = bg >> 1, g = bg & 1;
    int tid = threadIdx.x;
    int tq  = tid & 127;                  // w-quad index (w = 4*tq..4*tq+3)
    int sub = tid >> 7;                   // 0..3: 16-row strip within chunk
    const float4* xr4 = (const float4*)xr;
    const float4* xi4 = (const float4*)xi;
    size_t base0 = (size_t)(b*4 + 2*g    ) * H_ * (W_/4);
    size_t base1 = (size_t)(b*4 + 2*g + 1) * H_ * (W_/4);
    int h0 = ch * 64 + sub * 16;
    float4 acc = make_float4(0.f, 0.f, 0.f, 0.f);
    #pragma unroll 4
    for(int h = h0; h < h0 + 16; h++){
        float4 r0 = xr4[base0 + (size_t)h*(W_/4) + tq];
        float4 i0 = xi4[base0 + (size_t)h*(W_/4) + tq];
        float4 r1 = xr4[base1 + (size_t)h*(W_/4) + tq];
        float4 i1 = xi4[base1 + (size_t)h*(W_/4) + tq];
        acc.x += fabsf(fabsf(r0.x) - fabsf(i1.x)) + fabsf(fabsf(r1.x) - fabsf(i0.x));
        acc.y += fabsf(fabsf(r0.y) - fabsf(i1.y)) + fabsf(fabsf(r1.y) - fabsf(i0.y));
        acc.z += fabsf(fabsf(r0.z) - fabsf(i1.z)) + fabsf(fabsf(r1.z) - fabsf(i0.z));
        acc.w += fabsf(fabsf(r0.w) - fabsf(i1.w)) + fabsf(fabsf(r1.w) - fabsf(i0.w));
    }
    ((float4*)g_part)[((size_t)bg * NPART + ch*4 + sub) * 128 + tq] = acc;
}

// ------- kernel 2: exact stable top-64, output SORTED by column index -------
__global__ void k_select(){
    __shared__ float d[W_];
    __shared__ unsigned selw[16];
    int bg = blockIdx.x;                  // 64 blocks
    int w  = threadIdx.x;
    float s = 0.f;
    #pragma unroll
    for(int p = 0; p < NPART; p++)        // fixed order -> deterministic
        s += g_part[((size_t)bg * NPART + p) * W_ + w];
    d[w] = s;
    __syncthreads();
    int rank = 0;
    const float4* d4 = (const float4*)d;
    #pragma unroll 4
    for(int j4 = 0; j4 < 128; j4++){
        float4 v = d4[j4];
        int j = 4*j4;
        rank += (v.x < s) || (v.x == s && j   < w);
        rank += (v.y < s) || (v.y == s && j+1 < w);
        rank += (v.z < s) || (v.z == s && j+2 < w);
        rank += (v.w < s) || (v.w == s && j+3 < w);
    }
    bool sel = rank < T_;
    unsigned m = __ballot_sync(0xffffffffu, sel);
    int wid = w >> 5, lane = w & 31;
    if(lane == 0) selw[wid] = m;
    __syncthreads();
    if(sel){
        int pos = __popc(m & ((1u << lane) - 1u));
        #pragma unroll
        for(int k = 0; k < 16; k++) if(k < wid) pos += __popc(selw[k]);
        g_sel[bg * T_ + pos] = w;         // sorted ascending in w
    }
}

// ------- kernel 3: ifft_H of 8 sorted-adjacent columns per block -------
__global__ void k_colifft(const float* __restrict__ xr, const float* __restrict__ xi){
    __shared__ __align__(16) float2 A[8][PITCH];
    __shared__ float2 tw[512];
    __shared__ int jcol[8];
    int tid = threadIdx.x;
    tw[tid] = g_tw[tid];
    int blk = blockIdx.x;                 // bc*8 + tg, 1024 blocks
    int bc  = blk >> 3;
    int tg  = blk & 7;
    int b = bc >> 2, c = bc & 3, g = c >> 1;
    if(tid < 8) jcol[tid] = g_sel[(b*2 + g) * T_ + tg*8 + tid];
    __syncthreads();
    // gather: warp = 4 rows x 8 sorted-adjacent columns -> few sectors/row
    int f2    = tid & 7;
    int hbase = tid >> 3;                 // 0..63
    int j     = jcol[f2];
    const float scale = 1.0f / 512.0f;
    size_t rowbase = (size_t)bc * H_ * W_;
    #pragma unroll
    for(int pass = 0; pass < 8; pass++){
        int h = hbase + 64*pass;
        size_t off = rowbase + (size_t)h * W_ + j;
        A[f2][h] = make_float2(xr[off] * scale, xi[off] * scale);
    }
    __syncthreads();
    int f = tid >> 6, u = tid & 63;
    fft512<+1>(A[f], tw, u);
    // transposed write of Y as float4 (two t's per store)
    float4* Y4 = (float4*)g_Y;
    int tp = tid & 3;
    #pragma unroll
    for(int pass = 0; pass < 4; pass++){
        int kk = (tid >> 2) + pass * 128;
        float2 v0 = A[2*tp    ][kk];
        float2 v1 = A[2*tp + 1][kk];
        Y4[((size_t)bc * H_ + kk) * (T_/2) + tg*4 + tp] = make_float4(v0.x, v0.y, v1.x, v1.y);
    }
}

// ------- kernel 4: scatter + fft_W + 0.5, float4 output stores -------
__global__ void k_rowfft(const float2* __restrict__ Y, float4* __restrict__ out4){
    __shared__ __align__(16) float2 A[8][PITCH];
    __shared__ float2 tw[512];
    __shared__ int jj[T_];
    int tid = threadIdx.x;
    tw[tid] = g_tw[tid];
    int blk = blockIdx.x;                 // bc*64 + hg, 8192 blocks
    int bc  = blk >> 6;
    int hg  = blk & 63;
    int b = bc >> 2, c = bc & 3, g = c >> 1;
    if(tid < T_) jj[tid] = g_sel[(b*2 + g) * T_ + tid];
    int f = tid >> 6, u = tid & 63;
    int h = hg * 8 + f;
    float4* Az = (float4*)(&A[f][0]);
    #pragma unroll
    for(int q = 0; q < 4; q++) Az[u + 64*q] = make_float4(0.f, 0.f, 0.f, 0.f);
    __syncthreads();
    // coalesced Y row read (64 consecutive float2), scatter via sorted jj
    float2 v = Y[((size_t)bc * H_ + h) * T_ + u];
    A[f][jj[u]] = v;
    __syncthreads();
    fft512<-1>(A[f], tw, u);
    float4* op = out4 + ((size_t)bc * H_ + h) * (W_/2);
    const float4* Ar = (const float4*)(&A[f][0]);
    #pragma unroll
    for(int q = 0; q < 4; q++){
        float4 v2 = Ar[u + 64*q];         // complex pair (2u+128q, 2u+128q+1)
        v2.x += 0.5f;                     // +0.5 on real parts
        v2.z += 0.5f;
        op[u + 64*q] = v2;
    }
}

extern "C" void kernel_launch(void* const* d_in, const int* in_sizes, int n_in,
                              void* d_out, int out_size){
    const float* xr = (const float*)d_in[0];
    const float* xi = (const float*)d_in[1];
    float4* out = (float4*)d_out;

    float2* Yp = nullptr;
    cudaGetSymbolAddress((void**)&Yp, g_Y);

    k_twinit <<<1, 512>>>();
    k_diff   <<<B_ * 2 * 8, 512>>>(xr, xi);
    k_select <<<B_ * 2, 512>>>();
    k_colifft<<<B_ * C_ * T_ / 8, 512>>>(xr, xi);
    k_rowfft <<<B_ * C_ * H_ / 8, 512>>>(Yp, out);
}

// round 3
// speedup vs baseline: 1.3114x; 1.2542x over previous
#include <cuda_runtime.h>
#include <cstdint>

#define B_ 32
#define C_ 4
#define H_ 512
#define W_ 512
#define T_ 64
#define NPART 32
#define PITCH 514
// conflict-free smem swizzle: bank bits become (b0^b3, b1^b4, b2^b5, b3^b6)
#define SW(i) ((i) ^ (((i) >> 3) & 15))

// ------- scratch (static device globals; no allocation) -------
__device__ float  g_part[B_ * 2 * NPART * W_];
__device__ int    g_sel [B_ * 2 * T_];           // selected cols per (b,g), SORTED by j
__device__ float2 g_Xc  [B_ * C_ * H_ * T_];     // gathered selected cols, (bc, h, t), pre-scaled
__device__ float2 g_Y   [B_ * C_ * H_ * T_];     // ifft_H result, (bc, h=k, t)
__device__ float2 g_tw  [512];                   // e^{-2pi i n/512}

// ------- complex helpers -------
__device__ __forceinline__ float2 cadd(float2 a, float2 b){ return make_float2(a.x+b.x, a.y+b.y); }
__device__ __forceinline__ float2 csub(float2 a, float2 b){ return make_float2(a.x-b.x, a.y-b.y); }
__device__ __forceinline__ float2 cmul(float2 a, float2 b){
    return make_float2(fmaf(a.x, b.x, -a.y*b.y), fmaf(a.x, b.y, a.y*b.x));
}
template<int SGN> __device__ __forceinline__ float2 mulj(float2 a){
    return (SGN > 0) ? make_float2(-a.y, a.x) : make_float2(a.y, -a.x);
}

template<int SGN> __device__ __forceinline__
void dft4(float2 x0, float2 x1, float2 x2, float2 x3, float2* y){
    float2 t0 = cadd(x0, x2), t1 = csub(x0, x2);
    float2 t2 = cadd(x1, x3), t3 = csub(x1, x3);
    y[0] = cadd(t0, t2);  y[2] = csub(t0, t2);
    float2 j3 = mulj<SGN>(t3);
    y[1] = cadd(t1, j3);  y[3] = csub(t1, j3);
}

template<int SGN> __device__ __forceinline__
void dft8(const float2* a, float2* b){
    float2 E[4], O[4];
    dft4<SGN>(a[0], a[2], a[4], a[6], E);
    dft4<SGN>(a[1], a[3], a[5], a[7], O);
    const float c = 0.70710678118654752440f;
    const float sc = (SGN > 0) ? c : -c;
    float2 o1 = cmul(O[1], make_float2( c, sc));
    float2 o2 = mulj<SGN>(O[2]);
    float2 o3 = cmul(O[3], make_float2(-c, sc));
    b[0] = cadd(E[0], O[0]);  b[4] = csub(E[0], O[0]);
    b[1] = cadd(E[1], o1);    b[5] = csub(E[1], o1);
    b[2] = cadd(E[2], o2);    b[6] = csub(E[2], o2);
    b[3] = cadd(E[3], o3);    b[7] = csub(E[3], o3);
}

// 512-pt FFT over swizzled A[0..511] (one per 64 threads). Natural-order output.
// tw64[u]=e^{-2pi i u/512} (u<64), tw8[n]=e^{-2pi i n/64} (n<8).
template<int SGN> __device__ __forceinline__
void fft512(float2* A, const float2* tw64, const float2* tw8, int u){
    float2 a[8], b[8];
    #pragma unroll
    for(int q = 0; q < 8; q++) a[q] = A[SW(u + 64*q)];
    dft8<SGN>(a, b);
    float2 w1 = tw64[u];
    if(SGN > 0) w1.y = -w1.y;
    float2 w = make_float2(1.f, 0.f);
    #pragma unroll
    for(int k0 = 0; k0 < 8; k0++){
        A[SW(u + 64*k0)] = cmul(b[k0], w);
        w = cmul(w, w1);
    }
    __syncthreads();
    int k0 = u >> 3, n2 = u & 7;
    int base = 64*k0;
    #pragma unroll
    for(int p = 0; p < 8; p++) a[p] = A[SW(base + n2 + 8*p)];
    dft8<SGN>(a, b);
    float2 w2 = tw8[n2];
    if(SGN > 0) w2.y = -w2.y;
    w = make_float2(1.f, 0.f);
    #pragma unroll
    for(int k1 = 0; k1 < 8; k1++){
        A[SW(base + n2 + 8*k1)] = cmul(b[k1], w);
        w = cmul(w, w2);
    }
    __syncthreads();
    int k1 = u & 7;
    #pragma unroll
    for(int n = 0; n < 8; n++) a[n] = A[SW(n + 8*k1 + 64*k0)];
    dft8<SGN>(a, b);
    __syncthreads();
    #pragma unroll
    for(int k2 = 0; k2 < 8; k2++) A[SW(k0 + 8*k1 + 64*k2)] = b[k2];
    __syncthreads();
}

// load per-block twiddle tables (call with tid, then caller syncs)
__device__ __forceinline__ void load_tw(float2* tw64, float2* tw8, int tid){
    if(tid < 64) tw64[tid] = g_tw[tid];
    if(tid < 8)  tw8[tid]  = g_tw[8*tid];
}

// ------- kernel 0: twiddle init -------
__global__ void k_twinit(){
    int n = threadIdx.x;
    float s, c;
    sincospif((float)n * (1.0f/256.0f), &s, &c);
    g_tw[n] = make_float2(c, -s);
}

// ------- kernel 1: diff partials, float4 loads -------
__global__ void k_diff(const float* __restrict__ xr, const float* __restrict__ xi){
    int blk = blockIdx.x;                 // bg*8 + ch, 512 blocks
    int ch  = blk & 7;
    int bg  = blk >> 3;
    int b   = bg >> 1, g = bg & 1;
    int tid = threadIdx.x;
    int tq  = tid & 127;
    int sub = tid >> 7;
    const float4* xr4 = (const float4*)xr;
    const float4* xi4 = (const float4*)xi;
    size_t base0 = (size_t)(b*4 + 2*g    ) * H_ * (W_/4);
    size_t base1 = (size_t)(b*4 + 2*g + 1) * H_ * (W_/4);
    int h0 = ch * 64 + sub * 16;
    float4 acc = make_float4(0.f, 0.f, 0.f, 0.f);
    #pragma unroll 4
    for(int h = h0; h < h0 + 16; h++){
        float4 r0 = xr4[base0 + (size_t)h*(W_/4) + tq];
        float4 i0 = xi4[base0 + (size_t)h*(W_/4) + tq];
        float4 r1 = xr4[base1 + (size_t)h*(W_/4) + tq];
        float4 i1 = xi4[base1 + (size_t)h*(W_/4) + tq];
        acc.x += fabsf(fabsf(r0.x) - fabsf(i1.x)) + fabsf(fabsf(r1.x) - fabsf(i0.x));
        acc.y += fabsf(fabsf(r0.y) - fabsf(i1.y)) + fabsf(fabsf(r1.y) - fabsf(i0.y));
        acc.z += fabsf(fabsf(r0.z) - fabsf(i1.z)) + fabsf(fabsf(r1.z) - fabsf(i0.z));
        acc.w += fabsf(fabsf(r0.w) - fabsf(i1.w)) + fabsf(fabsf(r1.w) - fabsf(i0.w));
    }
    ((float4*)g_part)[((size_t)bg * NPART + ch*4 + sub) * 128 + tq] = acc;
}

// ------- kernel 2: exact stable top-64, output SORTED by column index -------
__global__ void k_select(){
    __shared__ float d[W_];
    __shared__ unsigned selw[16];
    int bg = blockIdx.x;                  // 64 blocks
    int w  = threadIdx.x;
    float s = 0.f;
    #pragma unroll
    for(int p = 0; p < NPART; p++)
        s += g_part[((size_t)bg * NPART + p) * W_ + w];
    d[w] = s;
    __syncthreads();
    int rank = 0;
    const float4* d4 = (const float4*)d;
    #pragma unroll 4
    for(int j4 = 0; j4 < 128; j4++){
        float4 v = d4[j4];
        int j = 4*j4;
        rank += (v.x < s) || (v.x == s && j   < w);
        rank += (v.y < s) || (v.y == s && j+1 < w);
        rank += (v.z < s) || (v.z == s && j+2 < w);
        rank += (v.w < s) || (v.w == s && j+3 < w);
    }
    bool sel = rank < T_;
    unsigned m = __ballot_sync(0xffffffffu, sel);
    int wid = w >> 5, lane = w & 31;
    if(lane == 0) selw[wid] = m;
    __syncthreads();
    if(sel){
        int pos = __popc(m & ((1u << lane) - 1u));
        #pragma unroll
        for(int k = 0; k < 16; k++) if(k < wid) pos += __popc(selw[k]);
        g_sel[bg * T_ + pos] = w;         // ascending j
    }
}

// ------- kernel 3a: gather selected columns -> compact Xc (each row fetched once) -------
__global__ void k_gather(const float* __restrict__ xr, const float* __restrict__ xi){
    __shared__ int jj[T_];
    int blk = blockIdx.x;                 // bc*8 + hc, 1024 blocks
    int bc  = blk >> 3;
    int hc  = blk & 7;
    int b = bc >> 2, c = bc & 3, g = c >> 1;
    int tid = threadIdx.x;
    if(tid < T_) jj[tid] = g_sel[(b*2 + g) * T_ + tid];
    __syncthreads();
    int t  = tid & 63;
    int hl = tid >> 6;                    // 0..7
    int j  = jj[t];
    const float scale = 1.0f / 512.0f;
    size_t rowbase = (size_t)bc * H_ * W_;
    #pragma unroll
    for(int pass = 0; pass < 8; pass++){
        int h = hc*64 + hl*8 + pass;
        size_t off = rowbase + (size_t)h * W_ + j;
        g_Xc[((size_t)bc * H_ + h) * T_ + t] = make_float2(xr[off] * scale, xi[off] * scale);
    }
}

// ------- kernel 3b: ifft_H over compact columns (fully coalesced) -------
__global__ void k_colfft(){
    __shared__ __align__(16) float2 A[8][PITCH];
    __shared__ float2 tw64[64];
    __shared__ float2 tw8[8];
    int tid = threadIdx.x;
    load_tw(tw64, tw8, tid);
    int blk = blockIdx.x;                 // bc*8 + tg, 1024 blocks
    int bc  = blk >> 3;
    int tg  = blk & 7;
    // stage in: 8 columns (t = tg*8 + c8) x 512 h
    int c8 = tid & 7;
    int hb = tid >> 3;                    // 0..63
    #pragma unroll
    for(int pass = 0; pass < 8; pass++){
        int h = hb + 64*pass;
        A[c8][SW(h)] = g_Xc[((size_t)bc * H_ + h) * T_ + tg*8 + c8];
    }
    __syncthreads();
    int f = tid >> 6, u = tid & 63;
    fft512<+1>(A[f], tw64, tw8, u);
    // transposed float4 write of Y (two adjacent t per store)
    float4* Y4 = (float4*)g_Y;
    int tp = tid & 3;
    #pragma unroll
    for(int pass = 0; pass < 4; pass++){
        int kk = (tid >> 2) + pass * 128;
        float2 v0 = A[2*tp    ][SW(kk)];
        float2 v1 = A[2*tp + 1][SW(kk)];
        Y4[((size_t)bc * H_ + kk) * (T_/2) + tg*4 + tp] = make_float4(v0.x, v0.y, v1.x, v1.y);
    }
}

// ------- kernel 4: scatter + fft_W + 0.5 -------
__global__ void k_rowfft(const float2* __restrict__ Y, float2* __restrict__ out){
    __shared__ __align__(16) float2 A[8][PITCH];
    __shared__ float2 tw64[64];
    __shared__ float2 tw8[8];
    __shared__ int jj[T_];
    int tid = threadIdx.x;
    load_tw(tw64, tw8, tid);
    int blk = blockIdx.x;                 // bc*64 + hg, 8192 blocks
    int bc  = blk >> 6;
    int hg  = blk & 63;
    int b = bc >> 2, c = bc & 3, g = c >> 1;
    if(tid < T_) jj[tid] = g_sel[(b*2 + g) * T_ + tid];
    int f = tid >> 6, u = tid & 63;
    int h = hg * 8 + f;
    float4* Az = (float4*)(&A[f][0]);
    #pragma unroll
    for(int q = 0; q < 4; q++) Az[u + 64*q] = make_float4(0.f, 0.f, 0.f, 0.f);
    __syncthreads();
    float2 v = Y[((size_t)bc * H_ + h) * T_ + u];
    A[f][SW(jj[u])] = v;
    __syncthreads();
    fft512<-1>(A[f], tw64, tw8, u);
    float2* op = out + ((size_t)bc * H_ + h) * W_;
    #pragma unroll
    for(int q = 0; q < 8; q++){
        float2 r = A[f][SW(u + 64*q)];
        r.x += 0.5f;
        op[u + 64*q] = r;
    }
}

extern "C" void kernel_launch(void* const* d_in, const int* in_sizes, int n_in,
                              void* d_out, int out_size){
    const float* xr = (const float*)d_in[0];
    const float* xi = (const float*)d_in[1];
    float2* out = (float2*)d_out;

    float2* Yp = nullptr;
    cudaGetSymbolAddress((void**)&Yp, g_Y);

    k_twinit <<<1, 512>>>();
    k_diff   <<<B_ * 2 * 8, 512>>>(xr, xi);
    k_select <<<B_ * 2, 512>>>();
    k_gather <<<B_ * C_ * 8, 512>>>(xr, xi);
    k_colfft <<<B_ * C_ * 8, 512>>>();
    k_rowfft <<<B_ * C_ * H_ / 8, 512>>>(Yp, out);
}

// round 6
// speedup vs baseline: 1.4191x; 1.0821x over previous
#include <cuda_runtime.h>
#include <cstdint>

#define B_ 32
#define C_ 4
#define H_ 512
#define W_ 512
#define T_ 64
#define NPART 64
#define PITCH 514
// conflict-free smem swizzle
#define SW(i) ((i) ^ (((i) >> 3) & 15))

// ------- scratch (static device globals; no allocation) -------
__device__ float  g_part[B_ * 2 * NPART * W_];
__device__ int    g_sel [B_ * 2 * T_];           // selected cols per (b,g), SORTED by j
__device__ float2 g_Xc  [B_ * C_ * H_ * T_];     // gathered selected cols, (bc, h, t), pre-scaled
__device__ float2 g_Y   [B_ * C_ * H_ * T_];     // ifft_H result, (bc, k, t)
__device__ float2 g_tw  [512];                   // e^{-2pi i n/512}

// ------- complex helpers -------
__device__ __forceinline__ float2 cadd(float2 a, float2 b){ return make_float2(a.x+b.x, a.y+b.y); }
__device__ __forceinline__ float2 csub(float2 a, float2 b){ return make_float2(a.x-b.x, a.y-b.y); }
__device__ __forceinline__ float2 cmul(float2 a, float2 b){
    return make_float2(fmaf(a.x, b.x, -a.y*b.y), fmaf(a.x, b.y, a.y*b.x));
}
template<int SGN> __device__ __forceinline__ float2 mulj(float2 a){
    return (SGN > 0) ? make_float2(-a.y, a.x) : make_float2(a.y, -a.x);
}

template<int SGN> __device__ __forceinline__
void dft4(float2 x0, float2 x1, float2 x2, float2 x3, float2* y){
    float2 t0 = cadd(x0, x2), t1 = csub(x0, x2);
    float2 t2 = cadd(x1, x3), t3 = csub(x1, x3);
    y[0] = cadd(t0, t2);  y[2] = csub(t0, t2);
    float2 j3 = mulj<SGN>(t3);
    y[1] = cadd(t1, j3);  y[3] = csub(t1, j3);
}

template<int SGN> __device__ __forceinline__
void dft8(const float2* a, float2* b){
    float2 E[4], O[4];
    dft4<SGN>(a[0], a[2], a[4], a[6], E);
    dft4<SGN>(a[1], a[3], a[5], a[7], O);
    const float c = 0.70710678118654752440f;
    const float sc = (SGN > 0) ? c : -c;
    float2 o1 = cmul(O[1], make_float2( c, sc));
    float2 o2 = mulj<SGN>(O[2]);
    float2 o3 = cmul(O[3], make_float2(-c, sc));
    b[0] = cadd(E[0], O[0]);  b[4] = csub(E[0], O[0]);
    b[1] = cadd(E[1], o1);    b[5] = csub(E[1], o1);
    b[2] = cadd(E[2], o2);    b[6] = csub(E[2], o2);
    b[3] = cadd(E[3], o3);    b[7] = csub(E[3], o3);
}

// stages 1+2 of 512-pt FFT over swizzled A (one FFT per 64 threads).
// Ends with stage-2 results in A and a trailing __syncthreads.
template<int SGN> __device__ __forceinline__
void fft512_s12(float2* A, const float2* tw64, const float2* tw8, int u){
    float2 a[8], b[8];
    #pragma unroll
    for(int q = 0; q < 8; q++) a[q] = A[SW(u + 64*q)];
    dft8<SGN>(a, b);
    float2 w1 = tw64[u];
    if(SGN > 0) w1.y = -w1.y;
    float2 w = make_float2(1.f, 0.f);
    #pragma unroll
    for(int k0 = 0; k0 < 8; k0++){
        A[SW(u + 64*k0)] = cmul(b[k0], w);
        w = cmul(w, w1);
    }
    __syncthreads();
    int k0 = u >> 3, n2 = u & 7;
    int base = 64*k0;
    #pragma unroll
    for(int p = 0; p < 8; p++) a[p] = A[SW(base + n2 + 8*p)];
    dft8<SGN>(a, b);
    float2 w2 = tw8[n2];
    if(SGN > 0) w2.y = -w2.y;
    w = make_float2(1.f, 0.f);
    #pragma unroll
    for(int k1 = 0; k1 < 8; k1++){
        A[SW(base + n2 + 8*k1)] = cmul(b[k1], w);
        w = cmul(w, w2);
    }
    __syncthreads();
}

__device__ __forceinline__ void load_tw(float2* tw64, float2* tw8, int tid){
    if(tid < 64) tw64[tid] = g_tw[tid];
    if(tid < 8)  tw8[tid]  = g_tw[8*tid];
}

// ------- kernel 0: twiddle init -------
__global__ void k_twinit(){
    int n = threadIdx.x;
    if(n < 512){
        float s, c;
        sincospif((float)n * (1.0f/256.0f), &s, &c);
        g_tw[n] = make_float2(c, -s);
    }
}

// ------- kernel 1: diff partials (1024 blocks, 32-row chunks) -------
__global__ void k_diff(const float* __restrict__ xr, const float* __restrict__ xi){
    int blk = blockIdx.x;                 // bg*16 + ch, 1024 blocks
    int ch  = blk & 15;
    int bg  = blk >> 4;
    int b   = bg >> 1, g = bg & 1;
    int tid = threadIdx.x;
    int tq  = tid & 127;
    int sub = tid >> 7;                   // 0..3 -> 8 rows each
    const float4* xr4 = (const float4*)xr;
    const float4* xi4 = (const float4*)xi;
    size_t base0 = (size_t)(b*4 + 2*g    ) * H_ * (W_/4);
    size_t base1 = (size_t)(b*4 + 2*g + 1) * H_ * (W_/4);
    int h0 = ch * 32 + sub * 8;
    float4 acc = make_float4(0.f, 0.f, 0.f, 0.f);
    #pragma unroll
    for(int h = h0; h < h0 + 8; h++){
        float4 r0 = xr4[base0 + (size_t)h*(W_/4) + tq];
        float4 i0 = xi4[base0 + (size_t)h*(W_/4) + tq];
        float4 r1 = xr4[base1 + (size_t)h*(W_/4) + tq];
        float4 i1 = xi4[base1 + (size_t)h*(W_/4) + tq];
        acc.x += fabsf(fabsf(r0.x) - fabsf(i1.x)) + fabsf(fabsf(r1.x) - fabsf(i0.x));
        acc.y += fabsf(fabsf(r0.y) - fabsf(i1.y)) + fabsf(fabsf(r1.y) - fabsf(i0.y));
        acc.z += fabsf(fabsf(r0.z) - fabsf(i1.z)) + fabsf(fabsf(r1.z) - fabsf(i0.z));
        acc.w += fabsf(fabsf(r0.w) - fabsf(i1.w)) + fabsf(fabsf(r1.w) - fabsf(i0.w));
    }
    ((float4*)g_part)[((size_t)bg * NPART + ch*4 + sub) * 128 + tq] = acc;
}

// ------- kernel 2: exact stable top-64, output SORTED by column index -------
__global__ void k_select(){
    __shared__ float d[W_];
    __shared__ unsigned selw[16];
    int bg = blockIdx.x;                  // 64 blocks
    int w  = threadIdx.x;
    float s = 0.f;
    #pragma unroll 8
    for(int p = 0; p < NPART; p++)
        s += g_part[((size_t)bg * NPART + p) * W_ + w];
    d[w] = s;
    __syncthreads();
    int rank = 0;
    const float4* d4 = (const float4*)d;
    #pragma unroll 4
    for(int j4 = 0; j4 < 128; j4++){
        float4 v = d4[j4];
        int j = 4*j4;
        rank += (v.x < s) || (v.x == s && j   < w);
        rank += (v.y < s) || (v.y == s && j+1 < w);
        rank += (v.z < s) || (v.z == s && j+2 < w);
        rank += (v.w < s) || (v.w == s && j+3 < w);
    }
    bool sel = rank < T_;
    unsigned m = __ballot_sync(0xffffffffu, sel);
    int wid = w >> 5, lane = w & 31;
    if(lane == 0) selw[wid] = m;
    __syncthreads();
    if(sel){
        int pos = __popc(m & ((1u << lane) - 1u));
        #pragma unroll
        for(int k = 0; k < 16; k++) if(k < wid) pos += __popc(selw[k]);
        g_sel[bg * T_ + pos] = w;         // ascending j
    }
}

// ------- kernel 3a: gather selected columns -> compact Xc -------
__global__ void k_gather(const float* __restrict__ xr, const float* __restrict__ xi){
    __shared__ int jj[T_];
    int blk = blockIdx.x;                 // bc*8 + hc, 1024 blocks
    int bc  = blk >> 3;
    int hc  = blk & 7;
    int b = bc >> 2, c = bc & 3, g = c >> 1;
    int tid = threadIdx.x;
    if(tid < T_) jj[tid] = g_sel[(b*2 + g) * T_ + tid];
    __syncthreads();
    int t  = tid & 63;
    int hl = tid >> 6;                    // 0..7
    int j  = jj[t];
    const float scale = 1.0f / 512.0f;
    size_t rowbase = (size_t)bc * H_ * W_;
    #pragma unroll
    for(int pass = 0; pass < 8; pass++){
        int h = hc*64 + hl*8 + pass;
        size_t off = rowbase + (size_t)h * W_ + j;
        g_Xc[((size_t)bc * H_ + h) * T_ + t] = make_float2(xr[off] * scale, xi[off] * scale);
    }
}

// ------- kernel 3b: ifft_H over compact columns, transposed Y write -------
__global__ void k_colfft(){
    __shared__ __align__(16) float2 A[8][PITCH];
    __shared__ float2 tw64[64];
    __shared__ float2 tw8[8];
    int tid = threadIdx.x;
    load_tw(tw64, tw8, tid);
    int blk = blockIdx.x;                 // bc*8 + tg, 1024 blocks
    int bc  = blk >> 3;
    int tg  = blk & 7;
    int c8 = tid & 7;
    int hb = tid >> 3;                    // 0..63
    #pragma unroll
    for(int pass = 0; pass < 8; pass++){
        int h = hb + 64*pass;
        A[c8][SW(h)] = g_Xc[((size_t)bc * H_ + h) * T_ + tg*8 + c8];
    }
    __syncthreads();
    int f = tid >> 6, u = tid & 63;
    fft512_s12<+1>(A[f], tw64, tw8, u);
    // stage 3 + digit-reversed smem store (natural order), then transpose-out
    {
        float2 a[8], b2[8];
        int k0 = u >> 3, k1 = u & 7;
        #pragma unroll
        for(int n = 0; n < 8; n++) a[n] = A[f][SW(n + 8*k1 + 64*k0)];
        dft8<+1>(a, b2);
        __syncthreads();
        #pragma unroll
        for(int k2 = 0; k2 < 8; k2++) A[f][SW(k0 + 8*k1 + 64*k2)] = b2[k2];
    }
    __syncthreads();
    float4* Y4 = (float4*)g_Y;
    int tp = tid & 3;
    #pragma unroll
    for(int pass = 0; pass < 4; pass++){
        int kk = (tid >> 2) + pass * 128;
        float2 v0 = A[2*tp    ][SW(kk)];
        float2 v1 = A[2*tp + 1][SW(kk)];
        Y4[((size_t)bc * H_ + kk) * (T_/2) + tg*4 + tp] = make_float4(v0.x, v0.y, v1.x, v1.y);
    }
}

// ------- kernel 4: scatter + fft_W + 0.5, stage-3 direct register stores -------
__global__ void k_rowfft(const float2* __restrict__ Y, float2* __restrict__ out){
    __shared__ __align__(16) float2 A[8][PITCH];
    __shared__ float2 tw64[64];
    __shared__ float2 tw8[8];
    __shared__ int jj[T_];
    int tid = threadIdx.x;
    load_tw(tw64, tw8, tid);
    int blk = blockIdx.x;                 // bc*64 + hg, 8192 blocks
    int bc  = blk >> 6;
    int hg  = blk & 63;
    int b = bc >> 2, c = bc & 3, g = c >> 1;
    if(tid < T_) jj[tid] = g_sel[(b*2 + g) * T_ + tid];
    int f = tid >> 6, u = tid & 63;
    int h = hg * 8 + f;
    float4* Az = (float4*)(&A[f][0]);
    #pragma unroll
    for(int q = 0; q < 4; q++) Az[u + 64*q] = make_float4(0.f, 0.f, 0.f, 0.f);
    __syncthreads();
    float2 v = Y[((size_t)bc * H_ + h) * T_ + u];
    A[f][SW(jj[u])] = v;
    __syncthreads();
    fft512_s12<-1>(A[f], tw64, tw8, u);
    // stage 3: dft8 in registers, store straight to global (full-sector warp pattern)
    float2 a[8], b2[8];
    int k0 = u >> 3, k1 = u & 7;
    #pragma unroll
    for(int n = 0; n < 8; n++) a[n] = A[f][SW(n + 8*k1 + 64*k0)];
    dft8<-1>(a, b2);
    float2* op = out + ((size_t)bc * H_ + h) * W_ + (k0 + 8*k1);
    #pragma unroll
    for(int k2 = 0; k2 < 8; k2++){
        float2 r = b2[k2];
        r.x += 0.5f;
        op[64*k2] = r;
    }
}

extern "C" void kernel_launch(void* const* d_in, const int* in_sizes, int n_in,
                              void* d_out, int out_size){
    const float* xr = (const float*)d_in[0];
    const float* xi = (const float*)d_in[1];
    float2* out = (float2*)d_out;

    float2* Yp = nullptr;
    cudaGetSymbolAddress((void**)&Yp, g_Y);

    k_twinit <<<1, 512>>>();
    k_diff   <<<B_ * 2 * 16, 512>>>(xr, xi);
    k_select <<<B_ * 2, 512>>>();
    k_gather <<<B_ * C_ * 8, 512>>>(xr, xi);
    k_colfft <<<B_ * C_ * 8, 512>>>();
    k_rowfft <<<B_ * C_ * H_ / 8, 512>>>(Yp, out);
}